// round 4
// baseline (speedup 1.0000x reference)
#include <cuda_runtime.h>
#include <math.h>

// Dimensions fixed by the problem
#define ED  172          // edge_dim
#define TD  100          // time_dim
#define DQ  356          // embed(256) + time(100)
#define EMB 256          // embed_dim
#define TB  16           // batch rows per block
#define RP  20           // col-major row pitch (mult of 4 -> LDS.128 aligned; stride-20 banks OK)

// ---- folded-weight scratch (device globals: no allocations allowed) ----
__device__ float g_cv[DQ];                      // cos(t2v_b) rows of Wv + bv
__device__ __align__(16) float g_cpre1[EMB];    // cv@W2 + bo@fc1 + fc1_b
__device__ __align__(16) float g_c3[EMB];       // fc2_b@Wsum + lps_b + lpd_b
__device__ __align__(16) float g_Wsum[EMB * EMB];  // lp_src_w + lp_dst_w
__device__ __align__(16) float g_W2[DQ * EMB];     // Wo @ fc1_w
__device__ __align__(16) float g_W3[EMB * EMB];    // fc2_w @ Wsum
__device__ __align__(16) float g_M2[ED * EMB];     // Wv[256:428,:] @ W2

// ============================================================
// Precompute 1: g_cv, g_Wsum, g_W2   (quad-tiled along j)
// ============================================================
__global__ void __launch_bounds__(256) tgat_pre1(
    const float* __restrict__ Wv,    const float* __restrict__ bv,
    const float* __restrict__ t2v_b,
    const float* __restrict__ lps_w, const float* __restrict__ lpd_w,
    const float* __restrict__ Wo,    const float* __restrict__ fc1_w)
{
    const int JQ   = EMB / 4;             // 64 quads per row
    const int N_CV = DQ;                  // scalar items
    const int N_WS = (EMB * EMB) / 4;     // quad items
    const int N_W2 = DQ * JQ;             // quad items
    const int total = N_CV + N_WS + N_W2;
    const float4* lps4 = (const float4*)lps_w;
    const float4* lpd4 = (const float4*)lpd_w;
    const float4* fc14 = (const float4*)fc1_w;
    float4* Wsum4 = (float4*)g_Wsum;
    float4* W24   = (float4*)g_W2;

    for (int idx = blockIdx.x * blockDim.x + threadIdx.x; idx < total;
         idx += gridDim.x * blockDim.x) {
        if (idx < N_CV) {
            int j = idx;
            float s = bv[j];
            #pragma unroll 4
            for (int t = 0; t < TD; t++)
                s += cosf(t2v_b[t]) * Wv[(EMB + ED + t) * DQ + j];
            g_cv[j] = s;
        } else if (idx < N_CV + N_WS) {
            int i = idx - N_CV;
            float4 a = lps4[i], b = lpd4[i];
            Wsum4[i] = make_float4(a.x + b.x, a.y + b.y, a.z + b.z, a.w + b.w);
        } else {
            int q = idx - N_CV - N_WS;
            int i = q / JQ, jq = q - i * JQ;
            float4 s = make_float4(0.f, 0.f, 0.f, 0.f);
            const float* wo = Wo + i * DQ;
            #pragma unroll 4
            for (int k = 0; k < DQ; k++) {
                float a = wo[k];
                float4 f = fc14[k * JQ + jq];
                s.x = fmaf(a, f.x, s.x); s.y = fmaf(a, f.y, s.y);
                s.z = fmaf(a, f.z, s.z); s.w = fmaf(a, f.w, s.w);
            }
            W24[q] = s;
        }
    }
}

// ============================================================
// Precompute 2: g_W3, g_M2, g_cpre1, g_c3  (needs pre1 outputs)
// ============================================================
__global__ void __launch_bounds__(256) tgat_pre2(
    const float* __restrict__ Wv,
    const float* __restrict__ fc2_w, const float* __restrict__ fc2_b,
    const float* __restrict__ bo,
    const float* __restrict__ fc1_w, const float* __restrict__ fc1_b,
    const float* __restrict__ lps_b, const float* __restrict__ lpd_b)
{
    const int JQ   = EMB / 4;
    const int N_W3 = EMB * JQ;
    const int N_M2 = ED * JQ;
    const int N_CP = JQ;
    const int N_C3 = JQ;
    const int total = N_W3 + N_M2 + N_CP + N_C3;
    const float4* Wsum4 = (const float4*)g_Wsum;
    const float4* W24   = (const float4*)g_W2;
    const float4* fc14  = (const float4*)fc1_w;
    float4* W34 = (float4*)g_W3;
    float4* M24 = (float4*)g_M2;

    for (int idx = blockIdx.x * blockDim.x + threadIdx.x; idx < total;
         idx += gridDim.x * blockDim.x) {
        if (idx < N_W3) {
            int i = idx / JQ, jq = idx - i * JQ;
            float4 s = make_float4(0.f, 0.f, 0.f, 0.f);
            const float* f2 = fc2_w + i * EMB;
            #pragma unroll 4
            for (int k = 0; k < EMB; k++) {
                float a = f2[k];
                float4 w = Wsum4[k * JQ + jq];
                s.x = fmaf(a, w.x, s.x); s.y = fmaf(a, w.y, s.y);
                s.z = fmaf(a, w.z, s.z); s.w = fmaf(a, w.w, s.w);
            }
            W34[idx] = s;
        } else if (idx < N_W3 + N_M2) {
            int q = idx - N_W3;
            int e = q / JQ, jq = q - e * JQ;
            float4 s = make_float4(0.f, 0.f, 0.f, 0.f);
            const float* wv = Wv + (EMB + e) * DQ;
            #pragma unroll 4
            for (int i = 0; i < DQ; i++) {
                float a = wv[i];
                float4 w = W24[i * JQ + jq];
                s.x = fmaf(a, w.x, s.x); s.y = fmaf(a, w.y, s.y);
                s.z = fmaf(a, w.z, s.z); s.w = fmaf(a, w.w, s.w);
            }
            M24[q] = s;
        } else if (idx < N_W3 + N_M2 + N_CP) {
            int jq = idx - N_W3 - N_M2;
            const float4* fb4 = (const float4*)fc1_b;
            float4 s = fb4[jq];
            #pragma unroll 4
            for (int k = 0; k < DQ; k++) {
                float a = g_cv[k];
                float4 w = W24[k * JQ + jq];
                s.x = fmaf(a, w.x, s.x); s.y = fmaf(a, w.y, s.y);
                s.z = fmaf(a, w.z, s.z); s.w = fmaf(a, w.w, s.w);
            }
            #pragma unroll 4
            for (int i = 0; i < DQ; i++) {
                float a = bo[i];
                float4 f = fc14[i * JQ + jq];
                s.x = fmaf(a, f.x, s.x); s.y = fmaf(a, f.y, s.y);
                s.z = fmaf(a, f.z, s.z); s.w = fmaf(a, f.w, s.w);
            }
            ((float4*)g_cpre1)[jq] = s;
        } else {
            int jq = idx - N_W3 - N_M2 - N_CP;
            const float4* sb4 = (const float4*)lps_b;
            const float4* db4 = (const float4*)lpd_b;
            float4 s0 = sb4[jq], s1 = db4[jq];
            float4 s = make_float4(s0.x + s1.x, s0.y + s1.y, s0.z + s1.z, s0.w + s1.w);
            #pragma unroll 4
            for (int k = 0; k < EMB; k++) {
                float a = fc2_b[k];
                float4 w = Wsum4[k * JQ + jq];
                s.x = fmaf(a, w.x, s.x); s.y = fmaf(a, w.y, s.y);
                s.z = fmaf(a, w.z, s.z); s.w = fmaf(a, w.w, s.w);
            }
            ((float4*)g_c3)[jq] = s;
        }
    }
}

// ============================================================
// Main fused kernel. Block = 16 batch rows, 256 threads (8 warps).
// Warp w owns cols [32w, 32w+32); thread: rows r0..r0+3 (r0=(lane>>3)*4),
// cols c0..c0+3 (c0=w*32+(lane&7)*4). Activation tiles are COLUMN-major
// (pitch RP=20) so the 4-row activation fetch is one LDS.128.
//   stage1: h  = relu(edge @ M2 + cpre1)
//   stage2: hp = relu(h @ W3 + c3)
//   stage3: prob = sigmoid(hp . lpo_w + lpo_b)
// ============================================================
__global__ void __launch_bounds__(256) tgat_main(
    const float* __restrict__ edge,
    const float* __restrict__ lpo_w, const float* __restrict__ lpo_b,
    float* __restrict__ out, int B, int dup)
{
    __shared__ __align__(16) float sbuf[EMB * RP];  // 20.5 KB: edge tile then h tile (col-major)
    __shared__ float red[8 * TB];

    const int tid  = threadIdx.x;
    const int lane = tid & 31;
    const int w    = tid >> 5;
    const int lm8  = lane & 7;
    const int r0   = (lane >> 3) * 4;
    const int c0   = w * 32 + lm8 * 4;
    const int widx = c0 >> 2;
    const int b0   = blockIdx.x * TB;

    // ---- transpose-load edge tile: gmem [r][e] -> smem col-major [e][r] ----
    for (int i = tid; i < TB * ED; i += 256) {
        int r = i / ED, e = i - r * ED;        // consecutive tid -> consecutive e: gmem coalesced
        sbuf[e * RP + r] = edge[b0 * ED + i];
    }
    __syncthreads();

    float acc[4][4];
    {
        float4 cp = *(const float4*)(g_cpre1 + c0);
        #pragma unroll
        for (int i = 0; i < 4; i++) {
            acc[i][0] = cp.x; acc[i][1] = cp.y; acc[i][2] = cp.z; acc[i][3] = cp.w;
        }
    }

    // ---- stage 1: acc[i][j] += edge[r0+i][e] * M2[e][c0+j] ----
    {
        const float4* M2v = (const float4*)g_M2;
        #pragma unroll 2
        for (int e = 0; e < ED; e++) {
            float4 wv = M2v[e * (EMB / 4) + widx];          // LDG.128, L1/L2-resident
            float4 av = *(const float4*)(sbuf + e * RP + r0); // LDS.128 broadcast
            float a[4] = {av.x, av.y, av.z, av.w};
            #pragma unroll
            for (int i = 0; i < 4; i++) {
                acc[i][0] = fmaf(a[i], wv.x, acc[i][0]);
                acc[i][1] = fmaf(a[i], wv.y, acc[i][1]);
                acc[i][2] = fmaf(a[i], wv.z, acc[i][2]);
                acc[i][3] = fmaf(a[i], wv.w, acc[i][3]);
            }
        }
    }
    __syncthreads();   // edge tile dead

    // ---- h = relu(acc) -> col-major h tile [k][r] ----
    #pragma unroll
    for (int j = 0; j < 4; j++) {
        float4 hv = make_float4(fmaxf(acc[0][j], 0.f), fmaxf(acc[1][j], 0.f),
                                fmaxf(acc[2][j], 0.f), fmaxf(acc[3][j], 0.f));
        *(float4*)(sbuf + (c0 + j) * RP + r0) = hv;
    }
    __syncthreads();

    {
        float4 cc = *(const float4*)(g_c3 + c0);
        #pragma unroll
        for (int i = 0; i < 4; i++) {
            acc[i][0] = cc.x; acc[i][1] = cc.y; acc[i][2] = cc.z; acc[i][3] = cc.w;
        }
    }

    // ---- stage 2: acc[i][j] += h[r0+i][k] * W3[k][c0+j] ----
    {
        const float4* W3v = (const float4*)g_W3;
        #pragma unroll 2
        for (int k = 0; k < EMB; k++) {
            float4 wv = W3v[k * (EMB / 4) + widx];
            float4 av = *(const float4*)(sbuf + k * RP + r0);
            float a[4] = {av.x, av.y, av.z, av.w};
            #pragma unroll
            for (int i = 0; i < 4; i++) {
                acc[i][0] = fmaf(a[i], wv.x, acc[i][0]);
                acc[i][1] = fmaf(a[i], wv.y, acc[i][1]);
                acc[i][2] = fmaf(a[i], wv.z, acc[i][2]);
                acc[i][3] = fmaf(a[i], wv.w, acc[i][3]);
            }
        }
    }

    // ---- stage 3: relu, dot with lpo_w, reduce across col chunks ----
    {
        float4 wl = *(const float4*)(lpo_w + c0);
        float part[4];
        #pragma unroll
        for (int i = 0; i < 4; i++) {
            part[i] = fmaxf(acc[i][0], 0.f) * wl.x
                    + fmaxf(acc[i][1], 0.f) * wl.y
                    + fmaxf(acc[i][2], 0.f) * wl.z
                    + fmaxf(acc[i][3], 0.f) * wl.w;
        }
        #pragma unroll
        for (int off = 1; off < 8; off <<= 1) {
            #pragma unroll
            for (int i = 0; i < 4; i++)
                part[i] += __shfl_xor_sync(0xffffffffu, part[i], off);
        }
        if (lm8 == 0) {
            #pragma unroll
            for (int i = 0; i < 4; i++)
                red[w * TB + r0 + i] = part[i];
        }
    }
    __syncthreads();

    if (tid < TB) {
        float s = lpo_b[0];
        #pragma unroll
        for (int ww = 0; ww < 8; ww++) s += red[ww * TB + tid];
        float prob = 1.f / (1.f + expf(-s));
        int b = b0 + tid;
        if (b < B) {
            out[b] = prob;                // pos_out
            if (dup) out[B + b] = prob;   // neg_out (identical)
        }
    }
}

// ============================================================
// Launch. Input order (metadata):
//  0 src 1 dst 2 time 3 edge_feats 4 t2v_w 5 t2v_b
//  6 Wq 7 bq 8 Wk 9 bk 10 Wv 11 bv 12 Wo 13 bo
//  14 fc1_w 15 fc1_b 16 fc2_w 17 fc2_b
//  18 lp_src_w 19 lp_src_b 20 lp_dst_w 21 lp_dst_b 22 lp_out_w 23 lp_out_b
// ============================================================
extern "C" void kernel_launch(void* const* d_in, const int* in_sizes, int n_in,
                              void* d_out, int out_size)
{
    const float* edge  = (const float*)d_in[3];
    const float* t2v_b = (const float*)d_in[5];
    const float* Wv    = (const float*)d_in[10];
    const float* bv    = (const float*)d_in[11];
    const float* Wo    = (const float*)d_in[12];
    const float* bo    = (const float*)d_in[13];
    const float* fc1_w = (const float*)d_in[14];
    const float* fc1_b = (const float*)d_in[15];
    const float* fc2_w = (const float*)d_in[16];
    const float* fc2_b = (const float*)d_in[17];
    const float* lps_w = (const float*)d_in[18];
    const float* lps_b = (const float*)d_in[19];
    const float* lpd_w = (const float*)d_in[20];
    const float* lpd_b = (const float*)d_in[21];
    const float* lpo_w = (const float*)d_in[22];
    const float* lpo_b = (const float*)d_in[23];

    const int B = in_sizes[0];
    float* out = (float*)d_out;
    const int dup = (out_size >= 2 * B) ? 1 : 0;

    tgat_pre1<<<296, 256>>>(Wv, bv, t2v_b, lps_w, lpd_w, Wo, fc1_w);
    tgat_pre2<<<296, 256>>>(Wv, fc2_w, fc2_b, bo, fc1_w, fc1_b, lps_b, lpd_b);
    tgat_main<<<(B + TB - 1) / TB, 256>>>(edge, lpo_w, lpo_b, out, B, dup);
}

// round 5
// speedup vs baseline: 1.1714x; 1.1714x over previous
#include <cuda_runtime.h>
#include <math.h>

// Dimensions fixed by the problem
#define ED  172          // edge_dim
#define TD  100          // time_dim
#define DQ  356          // embed(256) + time(100)
#define EMB 256          // embed_dim
#define TB  16           // batch rows per block (main kernel)
#define RP  20           // col-major row pitch in main kernel

// ---- folded-weight scratch (device globals: no allocations allowed) ----
__device__ float g_u[DQ];                          // cv @ Wo + bo
__device__ __align__(16) float g_cpre1[EMB];       // u @ fc1 + fc1_b
__device__ __align__(16) float g_c3[EMB];          // fc2_b @ Wsum + lps_b + lpd_b
__device__ __align__(16) float g_Wsum[EMB * EMB];  // lp_src_w + lp_dst_w
__device__ __align__(16) float g_T[ED * DQ];       // Wv_e @ Wo
__device__ __align__(16) float g_W3[EMB * EMB];    // fc2_w @ Wsum
__device__ __align__(16) float g_M2[ED * EMB];     // T @ fc1

// ============================================================
// Tiled mini-GEMM: C[M,N] = A[M,K] @ B[K,N], 32x32 block tile,
// K staged in 16-deep smem tiles. 256 threads; thread = 4 rows x 1 col.
// ============================================================
__device__ __forceinline__ void fold_gemm_tile(
    const float* __restrict__ A, int lda, int M,
    const float* __restrict__ B, int ldb, int K, int N,
    float* __restrict__ C, int ldc,
    int tileM, int tileN, float* As /*[16*36]*/, float* Bs /*[16*33]*/)
{
    const int tid = threadIdx.x;
    const int m0  = (tid & 7) * 4;
    const int n   = tid >> 3;
    float acc[4] = {0.f, 0.f, 0.f, 0.f};

    for (int k0 = 0; k0 < K; k0 += 16) {
        #pragma unroll
        for (int p = 0; p < 2; p++) {
            int idx = tid + 256 * p;            // 0..511
            int kk = idx & 15, m = idx >> 4;    // m 0..31
            int gm = tileM + m, gk = k0 + kk;
            As[kk * 36 + m] = (gm < M && gk < K) ? A[gm * lda + gk] : 0.f;
        }
        #pragma unroll
        for (int p = 0; p < 2; p++) {
            int idx = tid + 256 * p;
            int nn = idx & 31, kk = idx >> 5;   // kk 0..15
            int gk = k0 + kk, gn = tileN + nn;
            Bs[kk * 33 + nn] = (gk < K && gn < N) ? B[gk * ldb + gn] : 0.f;
        }
        __syncthreads();
        #pragma unroll
        for (int kk = 0; kk < 16; kk++) {
            float4 a = *(const float4*)(As + kk * 36 + m0);  // LDS.128
            float  b = Bs[kk * 33 + n];                       // broadcast
            acc[0] = fmaf(a.x, b, acc[0]);
            acc[1] = fmaf(a.y, b, acc[1]);
            acc[2] = fmaf(a.z, b, acc[2]);
            acc[3] = fmaf(a.w, b, acc[3]);
        }
        __syncthreads();
    }
    int gn = tileN + n;
    if (gn < N) {
        #pragma unroll
        for (int i = 0; i < 4; i++) {
            int gm = tileM + m0 + i;
            if (gm < M) C[gm * ldc + gn] = acc[i];
        }
    }
}

// ============================================================
// Precompute A: T = Wv_e @ Wo ; Wsum = lps_w + lpd_w ; cv -> u
//   blocks [0, 72)  : T GEMM  (6 x 12 tiles of 32x32)
//   blocks [72, 88) : Wsum elementwise
//   block  88       : cv (cos fold) then u = cv@Wo + bo
// ============================================================
#define PA_T    72
#define PA_WS   16
#define PA_GRID (PA_T + PA_WS + 1)

__global__ void __launch_bounds__(256) tgat_preA(
    const float* __restrict__ Wv,    const float* __restrict__ bv,
    const float* __restrict__ t2v_b, const float* __restrict__ Wo,
    const float* __restrict__ bo,
    const float* __restrict__ lps_w, const float* __restrict__ lpd_w)
{
    __shared__ __align__(16) float As[16 * 36];
    __shared__ float Bs[16 * 33];
    __shared__ float cs[TD];
    __shared__ float cvs[DQ];

    const int bid = blockIdx.x;
    const int tid = threadIdx.x;

    if (bid < PA_T) {
        const int NT = 12;                        // ceil(356/32)
        int tm = (bid / NT) * 32, tn = (bid % NT) * 32;
        fold_gemm_tile(Wv + EMB * DQ, DQ, ED,     // A = Wv rows 256..427
                       Wo, DQ, DQ, DQ,            // B = Wo
                       g_T, DQ, tm, tn, As, Bs);
    } else if (bid < PA_T + PA_WS) {
        const float4* a4 = (const float4*)lps_w;
        const float4* b4 = (const float4*)lpd_w;
        float4* s4 = (float4*)g_Wsum;
        int nq = (EMB * EMB) / 4;
        for (int i = (bid - PA_T) * 256 + tid; i < nq; i += PA_WS * 256) {
            float4 a = a4[i], b = b4[i];
            s4[i] = make_float4(a.x + b.x, a.y + b.y, a.z + b.z, a.w + b.w);
        }
    } else {
        // cv[j] = bv[j] + sum_t cos(t2v_b[t]) * Wv[(428+t)*DQ + j]
        if (tid < TD) cs[tid] = cosf(t2v_b[tid]);
        __syncthreads();
        for (int j = tid; j < DQ; j += 256) {
            float s = bv[j];
            #pragma unroll 4
            for (int t = 0; t < TD; t++)
                s = fmaf(cs[t], Wv[(EMB + ED + t) * DQ + j], s);
            cvs[j] = s;
        }
        __syncthreads();
        // u[i] = bo[i] + sum_k cv[k] * Wo[k][i]
        for (int i = tid; i < DQ; i += 256) {
            float s = bo[i];
            #pragma unroll 4
            for (int k = 0; k < DQ; k++)
                s = fmaf(cvs[k], Wo[k * DQ + i], s);
            g_u[i] = s;
        }
    }
}

// ============================================================
// Precompute B: M2 = T @ fc1 ; W3 = fc2 @ Wsum ; cpre1 ; c3
//   blocks [0, 48)    : M2 GEMM (6 x 8 tiles)
//   blocks [48, 112)  : W3 GEMM (8 x 8 tiles)
//   block  112        : cpre1 = u@fc1 + fc1_b ; c3 = fc2_b@Wsum + bsum
// ============================================================
#define PB_M2   48
#define PB_W3   64
#define PB_GRID (PB_M2 + PB_W3 + 1)

__global__ void __launch_bounds__(256) tgat_preB(
    const float* __restrict__ fc1_w, const float* __restrict__ fc1_b,
    const float* __restrict__ fc2_w, const float* __restrict__ fc2_b,
    const float* __restrict__ lps_b, const float* __restrict__ lpd_b)
{
    __shared__ __align__(16) float As[16 * 36];
    __shared__ float Bs[16 * 33];

    const int bid = blockIdx.x;
    const int tid = threadIdx.x;

    if (bid < PB_M2) {
        const int NT = 8;                        // ceil(256/32)
        int tm = (bid / NT) * 32, tn = (bid % NT) * 32;
        fold_gemm_tile(g_T, DQ, ED,
                       fc1_w, EMB, DQ, EMB,
                       g_M2, EMB, tm, tn, As, Bs);
    } else if (bid < PB_M2 + PB_W3) {
        const int NT = 8;
        int b2 = bid - PB_M2;
        int tm = (b2 / NT) * 32, tn = (b2 % NT) * 32;
        fold_gemm_tile(fc2_w, EMB, EMB,
                       g_Wsum, EMB, EMB, EMB,
                       g_W3, EMB, tm, tn, As, Bs);
    } else {
        for (int j = tid; j < EMB; j += 256) {
            float s = fc1_b[j];
            #pragma unroll 4
            for (int i = 0; i < DQ; i++)
                s = fmaf(g_u[i], fc1_w[i * EMB + j], s);
            g_cpre1[j] = s;
            float s2 = lps_b[j] + lpd_b[j];
            #pragma unroll 4
            for (int k = 0; k < EMB; k++)
                s2 = fmaf(fc2_b[k], g_Wsum[k * EMB + j], s2);
            g_c3[j] = s2;
        }
    }
}

// ============================================================
// Main fused kernel (unchanged from R4). Block = 16 batch rows,
// 256 threads. Col-major activation tiles (pitch 20) -> LDS.128.
//   stage1: h  = relu(edge @ M2 + cpre1)
//   stage2: hp = relu(h @ W3 + c3)
//   stage3: prob = sigmoid(hp . lpo_w + lpo_b)
// ============================================================
__global__ void __launch_bounds__(256) tgat_main(
    const float* __restrict__ edge,
    const float* __restrict__ lpo_w, const float* __restrict__ lpo_b,
    float* __restrict__ out, int B, int dup)
{
    __shared__ __align__(16) float sbuf[EMB * RP];
    __shared__ float red[8 * TB];

    const int tid  = threadIdx.x;
    const int lane = tid & 31;
    const int w    = tid >> 5;
    const int lm8  = lane & 7;
    const int r0   = (lane >> 3) * 4;
    const int c0   = w * 32 + lm8 * 4;
    const int widx = c0 >> 2;
    const int b0   = blockIdx.x * TB;

    // transpose-load edge tile: gmem [r][e] -> smem col-major [e][r]
    for (int i = tid; i < TB * ED; i += 256) {
        int r = i / ED, e = i - r * ED;
        sbuf[e * RP + r] = edge[b0 * ED + i];
    }
    __syncthreads();

    float acc[4][4];
    {
        float4 cp = *(const float4*)(g_cpre1 + c0);
        #pragma unroll
        for (int i = 0; i < 4; i++) {
            acc[i][0] = cp.x; acc[i][1] = cp.y; acc[i][2] = cp.z; acc[i][3] = cp.w;
        }
    }

    // stage 1
    {
        const float4* M2v = (const float4*)g_M2;
        #pragma unroll 2
        for (int e = 0; e < ED; e++) {
            float4 wv = M2v[e * (EMB / 4) + widx];
            float4 av = *(const float4*)(sbuf + e * RP + r0);
            float a[4] = {av.x, av.y, av.z, av.w};
            #pragma unroll
            for (int i = 0; i < 4; i++) {
                acc[i][0] = fmaf(a[i], wv.x, acc[i][0]);
                acc[i][1] = fmaf(a[i], wv.y, acc[i][1]);
                acc[i][2] = fmaf(a[i], wv.z, acc[i][2]);
                acc[i][3] = fmaf(a[i], wv.w, acc[i][3]);
            }
        }
    }
    __syncthreads();

    // h = relu -> col-major h tile
    #pragma unroll
    for (int j = 0; j < 4; j++) {
        float4 hv = make_float4(fmaxf(acc[0][j], 0.f), fmaxf(acc[1][j], 0.f),
                                fmaxf(acc[2][j], 0.f), fmaxf(acc[3][j], 0.f));
        *(float4*)(sbuf + (c0 + j) * RP + r0) = hv;
    }
    __syncthreads();

    {
        float4 cc = *(const float4*)(g_c3 + c0);
        #pragma unroll
        for (int i = 0; i < 4; i++) {
            acc[i][0] = cc.x; acc[i][1] = cc.y; acc[i][2] = cc.z; acc[i][3] = cc.w;
        }
    }

    // stage 2
    {
        const float4* W3v = (const float4*)g_W3;
        #pragma unroll 2
        for (int k = 0; k < EMB; k++) {
            float4 wv = W3v[k * (EMB / 4) + widx];
            float4 av = *(const float4*)(sbuf + k * RP + r0);
            float a[4] = {av.x, av.y, av.z, av.w};
            #pragma unroll
            for (int i = 0; i < 4; i++) {
                acc[i][0] = fmaf(a[i], wv.x, acc[i][0]);
                acc[i][1] = fmaf(a[i], wv.y, acc[i][1]);
                acc[i][2] = fmaf(a[i], wv.z, acc[i][2]);
                acc[i][3] = fmaf(a[i], wv.w, acc[i][3]);
            }
        }
    }

    // stage 3
    {
        float4 wl = *(const float4*)(lpo_w + c0);
        float part[4];
        #pragma unroll
        for (int i = 0; i < 4; i++) {
            part[i] = fmaxf(acc[i][0], 0.f) * wl.x
                    + fmaxf(acc[i][1], 0.f) * wl.y
                    + fmaxf(acc[i][2], 0.f) * wl.z
                    + fmaxf(acc[i][3], 0.f) * wl.w;
        }
        #pragma unroll
        for (int off = 1; off < 8; off <<= 1) {
            #pragma unroll
            for (int i = 0; i < 4; i++)
                part[i] += __shfl_xor_sync(0xffffffffu, part[i], off);
        }
        if (lm8 == 0) {
            #pragma unroll
            for (int i = 0; i < 4; i++)
                red[w * TB + r0 + i] = part[i];
        }
    }
    __syncthreads();

    if (tid < TB) {
        float s = lpo_b[0];
        #pragma unroll
        for (int ww = 0; ww < 8; ww++) s += red[ww * TB + tid];
        float prob = 1.f / (1.f + expf(-s));
        int b = b0 + tid;
        if (b < B) {
            out[b] = prob;
            if (dup) out[B + b] = prob;
        }
    }
}

// ============================================================
// Launch. Input order (metadata):
//  0 src 1 dst 2 time 3 edge_feats 4 t2v_w 5 t2v_b
//  6 Wq 7 bq 8 Wk 9 bk 10 Wv 11 bv 12 Wo 13 bo
//  14 fc1_w 15 fc1_b 16 fc2_w 17 fc2_b
//  18 lp_src_w 19 lp_src_b 20 lp_dst_w 21 lp_dst_b 22 lp_out_w 23 lp_out_b
// ============================================================
extern "C" void kernel_launch(void* const* d_in, const int* in_sizes, int n_in,
                              void* d_out, int out_size)
{
    const float* edge  = (const float*)d_in[3];
    const float* t2v_b = (const float*)d_in[5];
    const float* Wv    = (const float*)d_in[10];
    const float* bv    = (const float*)d_in[11];
    const float* Wo    = (const float*)d_in[12];
    const float* bo    = (const float*)d_in[13];
    const float* fc1_w = (const float*)d_in[14];
    const float* fc1_b = (const float*)d_in[15];
    const float* fc2_w = (const float*)d_in[16];
    const float* fc2_b = (const float*)d_in[17];
    const float* lps_w = (const float*)d_in[18];
    const float* lps_b = (const float*)d_in[19];
    const float* lpd_w = (const float*)d_in[20];
    const float* lpd_b = (const float*)d_in[21];
    const float* lpo_w = (const float*)d_in[22];
    const float* lpo_b = (const float*)d_in[23];

    const int B = in_sizes[0];
    float* out = (float*)d_out;
    const int dup = (out_size >= 2 * B) ? 1 : 0;

    tgat_preA<<<PA_GRID, 256>>>(Wv, bv, t2v_b, Wo, bo, lps_w, lpd_w);
    tgat_preB<<<PB_GRID, 256>>>(fc1_w, fc1_b, fc2_w, fc2_b, lps_b, lpd_b);
    tgat_main<<<(B + TB - 1) / TB, 256>>>(edge, lpo_w, lpo_b, out, B, dup);
}

// round 6
// speedup vs baseline: 1.7213x; 1.4694x over previous
#include <cuda_runtime.h>
#include <math.h>

// Dimensions fixed by the problem
#define ED  172          // edge_dim
#define TD  100          // time_dim
#define DQ  356          // embed(256) + time(100)
#define EMB 256          // embed_dim
#define TB  16           // batch rows per block (main kernel)
#define RP  20           // col-major row pitch in main kernel
#define KT  32           // fold-GEMM k-tile depth

// ---- folded-weight scratch (device globals: no allocations allowed) ----
__device__ float g_cv[DQ];                         // bv + cos(t2v_b)@Wv_time
__device__ float g_u[DQ];                          // cv @ Wo + bo
__device__ __align__(16) float g_cpre1[EMB];       // u @ fc1 + fc1_b
__device__ __align__(16) float g_c3[EMB];          // fc2_b @ Wsum + lps_b + lpd_b
__device__ __align__(16) float g_Wsum[EMB * EMB];  // lp_src_w + lp_dst_w
__device__ __align__(16) float g_T[ED * DQ];       // Wv_e @ Wo
__device__ __align__(16) float g_W3[EMB * EMB];    // fc2_w @ Wsum
__device__ __align__(16) float g_M2[ED * EMB];     // T @ fc1

// ============================================================
// Tiled fold GEMM: C[M,N] = A[M,K] @ B[K,N]; 32x32 block tile,
// KT=32 k-staging with register prefetch (LDG for tile t+1 in
// flight while computing tile t). 256 threads; thread = 4r x 1c.
// ============================================================
__device__ __forceinline__ void fold_gemm_tile(
    const float* __restrict__ A, int lda, int M,
    const float* __restrict__ B, int ldb, int K, int N,
    float* __restrict__ C, int ldc,
    int tileM, int tileN, float* As /*[KT*36]*/, float* Bs /*[KT*33]*/)
{
    const int tid = threadIdx.x;
    const int m0  = (tid & 7) * 4;
    const int n   = tid >> 3;
    const int nk  = (K + KT - 1) / KT;
    float acc[4] = {0.f, 0.f, 0.f, 0.f};
    float ra[4], rb[4];

    // prefetch k-tile 0
    #pragma unroll
    for (int p = 0; p < 4; p++) {
        int idx = tid + 256 * p;
        int gm = tileM + (idx >> 5), gk = idx & 31;
        ra[p] = (gm < M && gk < K) ? A[gm * lda + gk] : 0.f;
        int gk2 = idx >> 5, gn = tileN + (idx & 31);
        rb[p] = (gk2 < K && gn < N) ? B[gk2 * ldb + gn] : 0.f;
    }

    for (int kt = 0; kt < nk; kt++) {
        __syncthreads();                // previous compute done; smem reusable
        #pragma unroll
        for (int p = 0; p < 4; p++) {
            int idx = tid + 256 * p;
            As[(idx & 31) * 36 + (idx >> 5)] = ra[p];  // [kk][m]
            Bs[(idx >> 5) * 33 + (idx & 31)] = rb[p];  // [kk][n]
        }
        __syncthreads();
        if (kt + 1 < nk) {              // prefetch next tile (overlaps compute)
            int k0n = (kt + 1) * KT;
            #pragma unroll
            for (int p = 0; p < 4; p++) {
                int idx = tid + 256 * p;
                int gm = tileM + (idx >> 5), gk = k0n + (idx & 31);
                ra[p] = (gm < M && gk < K) ? A[gm * lda + gk] : 0.f;
                int gk2 = k0n + (idx >> 5), gn = tileN + (idx & 31);
                rb[p] = (gk2 < K && gn < N) ? B[gk2 * ldb + gn] : 0.f;
            }
        }
        #pragma unroll
        for (int kk = 0; kk < KT; kk++) {
            float4 a = *(const float4*)(As + kk * 36 + m0);  // LDS.128 (broadcast groups)
            float  b = Bs[kk * 33 + n];                       // broadcast
            acc[0] = fmaf(a.x, b, acc[0]);
            acc[1] = fmaf(a.y, b, acc[1]);
            acc[2] = fmaf(a.z, b, acc[2]);
            acc[3] = fmaf(a.w, b, acc[3]);
        }
    }
    int gn = tileN + n;
    if (gn < N) {
        #pragma unroll
        for (int i = 0; i < 4; i++) {
            int gm = tileM + m0 + i;
            if (gm < M) C[gm * ldc + gn] = acc[i];
        }
    }
}

// ============================================================
// Parallel GEMV for constant-vector folds:
//   y[j] = bias1[j] (+ bias2[j]) + sum_k xs[k] * W[k*ldw + j]
// Block covers 32 columns (j0..j0+31); 8 k-slices x 32 lanes.
// xs must already be in smem; coalesced 128B W-row loads.
// ============================================================
__device__ __forceinline__ void fold_gemv32(
    const float* __restrict__ xs, const float* __restrict__ W, int ldw, int K,
    const float* __restrict__ bias1, const float* __restrict__ bias2,
    float* __restrict__ y, int N, int j0, float* part /*[8*33]*/)
{
    const int tid = threadIdx.x;
    const int jl = tid & 31, slice = tid >> 5;
    const int j = j0 + jl;
    const int chunk = (K + 7) >> 3;
    const int k0 = slice * chunk;
    const int k1 = (k0 + chunk < K) ? (k0 + chunk) : K;
    float s = 0.f;
    if (j < N) {
        #pragma unroll 8
        for (int k = k0; k < k1; k++)
            s = fmaf(xs[k], W[k * ldw + j], s);
    }
    part[slice * 33 + jl] = s;
    __syncthreads();
    if (slice == 0 && j < N) {
        float t = bias1[j];
        if (bias2) t += bias2[j];
        #pragma unroll
        for (int p = 0; p < 8; p++) t += part[p * 33 + jl];
        y[j] = t;
    }
}

// ============================================================
// P1: T = Wv_e @ Wo (72 blocks) ; Wsum (16) ; cv GEMV (12)
// ============================================================
#define P1_T   72
#define P1_WS  16
#define P1_CV  12
#define P1_GRID (P1_T + P1_WS + P1_CV)

__global__ void __launch_bounds__(256) tgat_preP1(
    const float* __restrict__ Wv,    const float* __restrict__ bv,
    const float* __restrict__ t2v_b, const float* __restrict__ Wo,
    const float* __restrict__ lps_w, const float* __restrict__ lpd_w)
{
    __shared__ __align__(16) float As[KT * 36];
    __shared__ float Bs[KT * 33];
    __shared__ float xs[TD];
    __shared__ float part[8 * 33];

    const int bid = blockIdx.x;
    const int tid = threadIdx.x;

    if (bid < P1_T) {
        const int NT = 12;                       // ceil(356/32)
        int tm = (bid / NT) * 32, tn = (bid % NT) * 32;
        fold_gemm_tile(Wv + EMB * DQ, DQ, ED,    // A = Wv rows 256..427
                       Wo, DQ, DQ, DQ,
                       g_T, DQ, tm, tn, As, Bs);
    } else if (bid < P1_T + P1_WS) {
        const float4* a4 = (const float4*)lps_w;
        const float4* b4 = (const float4*)lpd_w;
        float4* s4 = (float4*)g_Wsum;
        int nq = (EMB * EMB) / 4;
        for (int i = (bid - P1_T) * 256 + tid; i < nq; i += P1_WS * 256) {
            float4 a = a4[i], b = b4[i];
            s4[i] = make_float4(a.x + b.x, a.y + b.y, a.z + b.z, a.w + b.w);
        }
    } else {
        // cv[j] = bv[j] + sum_t cos(t2v_b[t]) * Wv[(428+t)*DQ + j]
        if (tid < TD) xs[tid] = cosf(t2v_b[tid]);
        __syncthreads();
        int j0 = (bid - P1_T - P1_WS) * 32;
        fold_gemv32(xs, Wv + (EMB + ED) * DQ, DQ, TD, bv, 0, g_cv, DQ, j0, part);
    }
}

// ============================================================
// P2: M2 = T @ fc1 (48) ; W3 = fc2 @ Wsum (64) ; u GEMV (12) ; c3 GEMV (8)
// ============================================================
#define P2_M2  48
#define P2_W3  64
#define P2_U   12
#define P2_C3  8
#define P2_GRID (P2_M2 + P2_W3 + P2_U + P2_C3)

__global__ void __launch_bounds__(256) tgat_preP2(
    const float* __restrict__ fc1_w, const float* __restrict__ fc2_w,
    const float* __restrict__ fc2_b, const float* __restrict__ Wo,
    const float* __restrict__ bo,
    const float* __restrict__ lps_b, const float* __restrict__ lpd_b)
{
    __shared__ __align__(16) float As[KT * 36];
    __shared__ float Bs[KT * 33];
    __shared__ float xs[DQ];
    __shared__ float part[8 * 33];

    const int bid = blockIdx.x;
    const int tid = threadIdx.x;

    if (bid < P2_M2) {
        const int NT = 8;                        // ceil(256/32)
        int tm = (bid / NT) * 32, tn = (bid % NT) * 32;
        fold_gemm_tile(g_T, DQ, ED,
                       fc1_w, EMB, DQ, EMB,
                       g_M2, EMB, tm, tn, As, Bs);
    } else if (bid < P2_M2 + P2_W3) {
        const int NT = 8;
        int b2 = bid - P2_M2;
        int tm = (b2 / NT) * 32, tn = (b2 % NT) * 32;
        fold_gemm_tile(fc2_w, EMB, EMB,
                       g_Wsum, EMB, EMB, EMB,
                       g_W3, EMB, tm, tn, As, Bs);
    } else if (bid < P2_M2 + P2_W3 + P2_U) {
        // u[i] = bo[i] + sum_k cv[k] * Wo[k*DQ + i]
        for (int k = tid; k < DQ; k += 256) xs[k] = g_cv[k];
        __syncthreads();
        int j0 = (bid - P2_M2 - P2_W3) * 32;
        fold_gemv32(xs, Wo, DQ, DQ, bo, 0, g_u, DQ, j0, part);
    } else {
        // c3[j] = lps_b[j] + lpd_b[j] + sum_k fc2_b[k] * Wsum[k*EMB + j]
        for (int k = tid; k < EMB; k += 256) xs[k] = fc2_b[k];
        __syncthreads();
        int j0 = (bid - P2_M2 - P2_W3 - P2_U) * 32;
        fold_gemv32(xs, g_Wsum, EMB, EMB, lps_b, lpd_b, g_c3, EMB, j0, part);
    }
}

// ============================================================
// P3: cpre1 = u @ fc1 + fc1_b  (8 blocks; needs g_u from P2)
// ============================================================
__global__ void __launch_bounds__(256) tgat_preP3(
    const float* __restrict__ fc1_w, const float* __restrict__ fc1_b)
{
    __shared__ float xs[DQ];
    __shared__ float part[8 * 33];
    const int tid = threadIdx.x;
    for (int k = tid; k < DQ; k += 256) xs[k] = g_u[k];
    __syncthreads();
    fold_gemv32(xs, fc1_w, EMB, DQ, fc1_b, 0, g_cpre1, EMB, blockIdx.x * 32, part);
}

// ============================================================
// Main fused kernel (unchanged from R4/R5). Block = 16 batch rows,
// 256 threads. Col-major activation tiles (pitch 20) -> LDS.128.
//   stage1: h  = relu(edge @ M2 + cpre1)
//   stage2: hp = relu(h @ W3 + c3)
//   stage3: prob = sigmoid(hp . lpo_w + lpo_b)
// ============================================================
__global__ void __launch_bounds__(256) tgat_main(
    const float* __restrict__ edge,
    const float* __restrict__ lpo_w, const float* __restrict__ lpo_b,
    float* __restrict__ out, int B, int dup)
{
    __shared__ __align__(16) float sbuf[EMB * RP];
    __shared__ float red[8 * TB];

    const int tid  = threadIdx.x;
    const int lane = tid & 31;
    const int w    = tid >> 5;
    const int lm8  = lane & 7;
    const int r0   = (lane >> 3) * 4;
    const int c0   = w * 32 + lm8 * 4;
    const int widx = c0 >> 2;
    const int b0   = blockIdx.x * TB;

    // transpose-load edge tile: gmem [r][e] -> smem col-major [e][r]
    for (int i = tid; i < TB * ED; i += 256) {
        int r = i / ED, e = i - r * ED;
        sbuf[e * RP + r] = edge[b0 * ED + i];
    }
    __syncthreads();

    float acc[4][4];
    {
        float4 cp = *(const float4*)(g_cpre1 + c0);
        #pragma unroll
        for (int i = 0; i < 4; i++) {
            acc[i][0] = cp.x; acc[i][1] = cp.y; acc[i][2] = cp.z; acc[i][3] = cp.w;
        }
    }

    // stage 1
    {
        const float4* M2v = (const float4*)g_M2;
        #pragma unroll 2
        for (int e = 0; e < ED; e++) {
            float4 wv = M2v[e * (EMB / 4) + widx];
            float4 av = *(const float4*)(sbuf + e * RP + r0);
            float a[4] = {av.x, av.y, av.z, av.w};
            #pragma unroll
            for (int i = 0; i < 4; i++) {
                acc[i][0] = fmaf(a[i], wv.x, acc[i][0]);
                acc[i][1] = fmaf(a[i], wv.y, acc[i][1]);
                acc[i][2] = fmaf(a[i], wv.z, acc[i][2]);
                acc[i][3] = fmaf(a[i], wv.w, acc[i][3]);
            }
        }
    }
    __syncthreads();

    // h = relu -> col-major h tile
    #pragma unroll
    for (int j = 0; j < 4; j++) {
        float4 hv = make_float4(fmaxf(acc[0][j], 0.f), fmaxf(acc[1][j], 0.f),
                                fmaxf(acc[2][j], 0.f), fmaxf(acc[3][j], 0.f));
        *(float4*)(sbuf + (c0 + j) * RP + r0) = hv;
    }
    __syncthreads();

    {
        float4 cc = *(const float4*)(g_c3 + c0);
        #pragma unroll
        for (int i = 0; i < 4; i++) {
            acc[i][0] = cc.x; acc[i][1] = cc.y; acc[i][2] = cc.z; acc[i][3] = cc.w;
        }
    }

    // stage 2
    {
        const float4* W3v = (const float4*)g_W3;
        #pragma unroll 2
        for (int k = 0; k < EMB; k++) {
            float4 wv = W3v[k * (EMB / 4) + widx];
            float4 av = *(const float4*)(sbuf + k * RP + r0);
            float a[4] = {av.x, av.y, av.z, av.w};
            #pragma unroll
            for (int i = 0; i < 4; i++) {
                acc[i][0] = fmaf(a[i], wv.x, acc[i][0]);
                acc[i][1] = fmaf(a[i], wv.y, acc[i][1]);
                acc[i][2] = fmaf(a[i], wv.z, acc[i][2]);
                acc[i][3] = fmaf(a[i], wv.w, acc[i][3]);
            }
        }
    }

    // stage 3
    {
        float4 wl = *(const float4*)(lpo_w + c0);
        float part[4];
        #pragma unroll
        for (int i = 0; i < 4; i++) {
            part[i] = fmaxf(acc[i][0], 0.f) * wl.x
                    + fmaxf(acc[i][1], 0.f) * wl.y
                    + fmaxf(acc[i][2], 0.f) * wl.z
                    + fmaxf(acc[i][3], 0.f) * wl.w;
        }
        #pragma unroll
        for (int off = 1; off < 8; off <<= 1) {
            #pragma unroll
            for (int i = 0; i < 4; i++)
                part[i] += __shfl_xor_sync(0xffffffffu, part[i], off);
        }
        if (lm8 == 0) {
            #pragma unroll
            for (int i = 0; i < 4; i++)
                red[w * TB + r0 + i] = part[i];
        }
    }
    __syncthreads();

    if (tid < TB) {
        float s = lpo_b[0];
        #pragma unroll
        for (int ww = 0; ww < 8; ww++) s += red[ww * TB + tid];
        float prob = 1.f / (1.f + expf(-s));
        int b = b0 + tid;
        if (b < B) {
            out[b] = prob;
            if (dup) out[B + b] = prob;
        }
    }
}

// ============================================================
// Launch. Input order (metadata):
//  0 src 1 dst 2 time 3 edge_feats 4 t2v_w 5 t2v_b
//  6 Wq 7 bq 8 Wk 9 bk 10 Wv 11 bv 12 Wo 13 bo
//  14 fc1_w 15 fc1_b 16 fc2_w 17 fc2_b
//  18 lp_src_w 19 lp_src_b 20 lp_dst_w 21 lp_dst_b 22 lp_out_w 23 lp_out_b
// ============================================================
extern "C" void kernel_launch(void* const* d_in, const int* in_sizes, int n_in,
                              void* d_out, int out_size)
{
    const float* edge  = (const float*)d_in[3];
    const float* t2v_b = (const float*)d_in[5];
    const float* Wv    = (const float*)d_in[10];
    const float* bv    = (const float*)d_in[11];
    const float* Wo    = (const float*)d_in[12];
    const float* bo    = (const float*)d_in[13];
    const float* fc1_w = (const float*)d_in[14];
    const float* fc1_b = (const float*)d_in[15];
    const float* fc2_w = (const float*)d_in[16];
    const float* fc2_b = (const float*)d_in[17];
    const float* lps_w = (const float*)d_in[18];
    const float* lps_b = (const float*)d_in[19];
    const float* lpd_w = (const float*)d_in[20];
    const float* lpd_b = (const float*)d_in[21];
    const float* lpo_w = (const float*)d_in[22];
    const float* lpo_b = (const float*)d_in[23];

    const int B = in_sizes[0];
    float* out = (float*)d_out;
    const int dup = (out_size >= 2 * B) ? 1 : 0;

    tgat_preP1<<<P1_GRID, 256>>>(Wv, bv, t2v_b, Wo, lps_w, lpd_w);
    tgat_preP2<<<P2_GRID, 256>>>(fc1_w, fc2_w, fc2_b, Wo, bo, lps_b, lpd_b);
    tgat_preP3<<<8, 256>>>(fc1_w, fc1_b);
    tgat_main<<<(B + TB - 1) / TB, 256>>>(edge, lpo_w, lpo_b, out, B, dup);
}